// round 5
// baseline (speedup 1.0000x reference)
#include <cuda_runtime.h>

// ---------------------------------------------------------------------------
// MPNEncoder: message-passing network, DEPTH=6, H=128.
//
// Restructured computation:
//   inp        = init_messages @ W_i                      (once)
//   attnei[a]  = sum_j attfea[a2attached[a,j]]            (once, loop-invariant)
//   bias2[b]   = inp[b] + (attnei[b2a[b]] - attfea[b2a[b2revb[b]]]) @ W_h[128:]
//   msg        = relu(inp)
//   5x: nei[a] = sum_j msg[a2nei[a,j]]
//       msg    = relu(bias2 + (nei[b2a] - msg[b2revb]) @ W_h[:128])
// ---------------------------------------------------------------------------

constexpr int NBb  = 500000;
constexpr int NAa  = 250000;
constexpr int DMSG = 165;
constexpr int DATT = 151;
constexpr int HH   = 128;

// Scratch (allocation-free rule: __device__ globals)
__device__ float g_bias2 [(size_t)NBb * HH];   // 256 MB
__device__ float g_msg0  [(size_t)NBb * HH];   // 256 MB
__device__ float g_msg1  [(size_t)NBb * HH];   // 256 MB
__device__ float g_nei   [(size_t)NAa * HH];   // 128 MB
__device__ float g_attnei[(size_t)NAa * DATT]; // 151 MB

typedef unsigned long long u64;

__device__ __forceinline__ u64 pack2(float lo, float hi) {
    u64 d;
    asm("mov.b64 %0, {%1, %2};" : "=l"(d) : "f"(lo), "f"(hi));
    return d;
}
__device__ __forceinline__ void unpack2(u64 v, float& lo, float& hi) {
    asm("mov.b64 {%0, %1}, %2;" : "=f"(lo), "=f"(hi) : "l"(v));
}
__device__ __forceinline__ void fma2(u64& d, u64 a, u64 b) {
    asm("fma.rn.f32x2 %0, %1, %2, %0;" : "+l"(d) : "l"(a), "l"(b));
}

// ---------------------------------------------------------------------------
// Shared GEMM inner loop: C[128,128] tile, A in smem [128][KP] row-major
// (KP odd => broadcast A loads conflict-free), B in smem [K][128].
// Thread (tx,ty) in 16x16 grid computes rows ty*8..+7, cols {4tx..4tx+3} and
// {64+4tx..64+4tx+3}  (two coalesced float4 groups).
// ---------------------------------------------------------------------------
template<int K, int KP>
__device__ __forceinline__ void gemm_tile(const float* __restrict__ sA,
                                          const float* __restrict__ sB,
                                          u64 (&acc)[8][4], int ty, int tx) {
    const float* pa = sA + ty * 8 * KP;
    #pragma unroll 4
    for (int k = 0; k < K; ++k) {
        float4 b0 = *(const float4*)(sB + k * HH + tx * 4);
        float4 b1 = *(const float4*)(sB + k * HH + 64 + tx * 4);
        u64 bd0 = pack2(b0.x, b0.y), bd1 = pack2(b0.z, b0.w);
        u64 bd2 = pack2(b1.x, b1.y), bd3 = pack2(b1.z, b1.w);
        #pragma unroll
        for (int i = 0; i < 8; ++i) {
            float av = pa[i * KP + k];
            u64 ad = pack2(av, av);
            fma2(acc[i][0], ad, bd0);
            fma2(acc[i][1], ad, bd1);
            fma2(acc[i][2], ad, bd2);
            fma2(acc[i][3], ad, bd3);
        }
    }
}

__device__ __forceinline__ void zero_acc(u64 (&acc)[8][4]) {
    #pragma unroll
    for (int i = 0; i < 8; ++i)
        #pragma unroll
        for (int j = 0; j < 4; ++j) acc[i][j] = 0ull;
}

// ---------------------------------------------------------------------------
// Kernel 1: inp = A @ W_i ; bias_out = inp ; msg_out = relu(inp)
// ---------------------------------------------------------------------------
__global__ void __launch_bounds__(256, 1) k_gemm_wi(
    const float* __restrict__ A, const float* __restrict__ W,
    float* __restrict__ bias_out, float* __restrict__ msg_out)
{
    extern __shared__ float sm[];
    float* sA = sm;                  // [128][DMSG]  (KP == DMSG, contiguous copy)
    float* sB = sm + 128 * DMSG;     // [DMSG][HH]
    const int tid = threadIdx.x;

    for (int i = tid; i < DMSG * HH; i += 256) sB[i] = W[i];

    const long row0 = (long)blockIdx.x * 128;
    const int nrows = min(128, NBb - (int)row0);
    const int total = nrows * DMSG;
    const float* Ab = A + row0 * DMSG;
    for (int i = tid; i < 128 * DMSG; i += 256) sA[i] = (i < total) ? Ab[i] : 0.f;
    __syncthreads();

    const int tx = tid & 15, ty = tid >> 4;
    u64 acc[8][4];
    zero_acc(acc);
    gemm_tile<DMSG, DMSG>(sA, sB, acc, ty, tx);

    #pragma unroll
    for (int i = 0; i < 8; ++i) {
        long r = row0 + ty * 8 + i;
        if (r < NBb) {
            float c0, c1, c2, c3, c4, c5, c6, c7;
            unpack2(acc[i][0], c0, c1); unpack2(acc[i][1], c2, c3);
            unpack2(acc[i][2], c4, c5); unpack2(acc[i][3], c6, c7);
            *(float4*)(bias_out + r * HH + tx * 4)      = make_float4(c0, c1, c2, c3);
            *(float4*)(bias_out + r * HH + 64 + tx * 4) = make_float4(c4, c5, c6, c7);
            *(float4*)(msg_out + r * HH + tx * 4) =
                make_float4(fmaxf(c0, 0.f), fmaxf(c1, 0.f), fmaxf(c2, 0.f), fmaxf(c3, 0.f));
            *(float4*)(msg_out + r * HH + 64 + tx * 4) =
                make_float4(fmaxf(c4, 0.f), fmaxf(c5, 0.f), fmaxf(c6, 0.f), fmaxf(c7, 0.f));
        }
    }
}

// ---------------------------------------------------------------------------
// Kernel 2: attnei[a] = sum_j attfea[a2attached[a,j]]   (warp per atom)
// ---------------------------------------------------------------------------
__global__ void __launch_bounds__(256) k_att_agg(
    const float* __restrict__ attfea, const int* __restrict__ a2att,
    float* __restrict__ attnei)
{
    const int warp = threadIdx.x >> 5, lane = threadIdx.x & 31;
    const int a = blockIdx.x * 8 + warp;
    if (a >= NAa) return;

    int idx[6];
    #pragma unroll
    for (int j = 0; j < 6; ++j) idx[j] = a2att[a * 6 + j];

    float acc[5] = {0.f, 0.f, 0.f, 0.f, 0.f};
    #pragma unroll
    for (int j = 0; j < 6; ++j) {
        const float* p = attfea + (long)idx[j] * DATT;
        #pragma unroll
        for (int t = 0; t < 5; ++t) {
            int c = t * 32 + lane;
            if (c < DATT) acc[t] += p[c];
        }
    }
    float* o = attnei + (long)a * DATT;
    #pragma unroll
    for (int t = 0; t < 5; ++t) {
        int c = t * 32 + lane;
        if (c < DATT) o[c] = acc[t];
    }
}

// ---------------------------------------------------------------------------
// Kernel 3: bias2 += (attnei[b2a[b]] - attfea[b2a[b2revb[b]]]) @ W_h[128:279]
// Gathered-A GEMM, K = DATT = 151.
// ---------------------------------------------------------------------------
__global__ void __launch_bounds__(256, 1) k_gemm_att(
    const float* __restrict__ attnei, const float* __restrict__ attfea,
    const float* __restrict__ Wh_att, const int* __restrict__ b2a,
    const int* __restrict__ b2revb, float* __restrict__ bias)
{
    extern __shared__ float sm[];
    float* sA = sm;                  // [128][DATT]
    float* sB = sm + 128 * DATT;     // [DATT][HH]
    const int tid = threadIdx.x;

    for (int i = tid; i < DATT * HH; i += 256) sB[i] = Wh_att[i];

    const long row0 = (long)blockIdx.x * 128;
    const int warp = tid >> 5, lane = tid & 31;
    for (int r = warp; r < 128; r += 8) {
        long b = row0 + r;
        bool valid = b < NBb;
        int ia = 0, ir = 0;
        if (valid) {
            ia = b2a[b];
            ir = b2a[b2revb[b]];
        }
        const float* pa = attnei + (long)ia * DATT;
        const float* pr = attfea + (long)ir * DATT;
        float* d = sA + r * DATT;
        for (int c = lane; c < DATT; c += 32)
            d[c] = valid ? (pa[c] - pr[c]) : 0.f;
    }
    __syncthreads();

    const int tx = tid & 15, ty = tid >> 4;
    u64 acc[8][4];
    zero_acc(acc);
    gemm_tile<DATT, DATT>(sA, sB, acc, ty, tx);

    #pragma unroll
    for (int i = 0; i < 8; ++i) {
        long r = row0 + ty * 8 + i;
        if (r < NBb) {
            float c0, c1, c2, c3, c4, c5, c6, c7;
            unpack2(acc[i][0], c0, c1); unpack2(acc[i][1], c2, c3);
            unpack2(acc[i][2], c4, c5); unpack2(acc[i][3], c6, c7);
            float4* p0 = (float4*)(bias + r * HH + tx * 4);
            float4* p1 = (float4*)(bias + r * HH + 64 + tx * 4);
            float4 o0 = *p0, o1 = *p1;
            o0.x += c0; o0.y += c1; o0.z += c2; o0.w += c3;
            o1.x += c4; o1.y += c5; o1.z += c6; o1.w += c7;
            *p0 = o0; *p1 = o1;
        }
    }
}

// ---------------------------------------------------------------------------
// Kernel 4: nei[a] = sum_j msg[a2nei[a,j]]   (warp per atom, float4 lanes)
// ---------------------------------------------------------------------------
__global__ void __launch_bounds__(256) k_nei_agg(
    const float* __restrict__ msg, const int* __restrict__ a2nei,
    float* __restrict__ nei)
{
    const int warp = threadIdx.x >> 5, lane = threadIdx.x & 31;
    const int a = blockIdx.x * 8 + warp;
    if (a >= NAa) return;

    int idx[6];
    #pragma unroll
    for (int j = 0; j < 6; ++j) idx[j] = a2nei[a * 6 + j];

    float4 acc = make_float4(0.f, 0.f, 0.f, 0.f);
    #pragma unroll
    for (int j = 0; j < 6; ++j) {
        float4 v = *(const float4*)(msg + (long)idx[j] * HH + lane * 4);
        acc.x += v.x; acc.y += v.y; acc.z += v.z; acc.w += v.w;
    }
    *(float4*)(nei + (long)a * HH + lane * 4) = acc;
}

// ---------------------------------------------------------------------------
// Kernel 5: msg_out = relu(bias2 + (nei[b2a] - msg_in[b2revb]) @ W_h[:128])
// Gathered-A GEMM, K = 128, KP = 129 (odd pad).
// ---------------------------------------------------------------------------
__global__ void __launch_bounds__(256, 1) k_gemm_msg(
    const float* __restrict__ nei, const float* __restrict__ msg_in,
    const float* __restrict__ Wh, const int* __restrict__ b2a,
    const int* __restrict__ b2revb, const float* __restrict__ bias,
    float* __restrict__ msg_out)
{
    constexpr int KP = HH + 1;       // 129
    extern __shared__ float sm[];
    float* sA = sm;                  // [128][KP]
    float* sB = sm + 128 * KP;       // [HH][HH]
    const int tid = threadIdx.x;

    for (int i = tid; i < HH * HH; i += 256) sB[i] = Wh[i];

    const long row0 = (long)blockIdx.x * 128;
    const int warp = tid >> 5, lane = tid & 31;
    for (int r = warp; r < 128; r += 8) {
        long b = row0 + r;
        bool valid = b < NBb;
        int ia = valid ? b2a[b] : 0;
        int ib = valid ? b2revb[b] : 0;
        float4 x = *(const float4*)(nei + (long)ia * HH + lane * 4);
        float4 y = *(const float4*)(msg_in + (long)ib * HH + lane * 4);
        float* d = sA + r * KP + lane * 4;
        d[0] = valid ? (x.x - y.x) : 0.f;
        d[1] = valid ? (x.y - y.y) : 0.f;
        d[2] = valid ? (x.z - y.z) : 0.f;
        d[3] = valid ? (x.w - y.w) : 0.f;
    }
    __syncthreads();

    const int tx = tid & 15, ty = tid >> 4;
    u64 acc[8][4];
    zero_acc(acc);
    gemm_tile<HH, KP>(sA, sB, acc, ty, tx);

    #pragma unroll
    for (int i = 0; i < 8; ++i) {
        long r = row0 + ty * 8 + i;
        if (r < NBb) {
            float c0, c1, c2, c3, c4, c5, c6, c7;
            unpack2(acc[i][0], c0, c1); unpack2(acc[i][1], c2, c3);
            unpack2(acc[i][2], c4, c5); unpack2(acc[i][3], c6, c7);
            float4 bb0 = *(const float4*)(bias + r * HH + tx * 4);
            float4 bb1 = *(const float4*)(bias + r * HH + 64 + tx * 4);
            *(float4*)(msg_out + r * HH + tx * 4) = make_float4(
                fmaxf(bb0.x + c0, 0.f), fmaxf(bb0.y + c1, 0.f),
                fmaxf(bb0.z + c2, 0.f), fmaxf(bb0.w + c3, 0.f));
            *(float4*)(msg_out + r * HH + 64 + tx * 4) = make_float4(
                fmaxf(bb1.x + c4, 0.f), fmaxf(bb1.y + c5, 0.f),
                fmaxf(bb1.z + c6, 0.f), fmaxf(bb1.w + c7, 0.f));
        }
    }
}

// ---------------------------------------------------------------------------
// Launch
// ---------------------------------------------------------------------------
extern "C" void kernel_launch(void* const* d_in, const int* in_sizes, int n_in,
                              void* d_out, int out_size) {
    (void)in_sizes; (void)n_in; (void)out_size;

    const float* init_messages = (const float*)d_in[0];
    const float* attfea        = (const float*)d_in[1];
    const float* W_i           = (const float*)d_in[2];
    const float* W_h           = (const float*)d_in[3];  // [279][128]
    const int*   a2nei         = (const int*)d_in[4];
    const int*   a2att         = (const int*)d_in[5];
    const int*   b2a           = (const int*)d_in[6];
    const int*   b2revb        = (const int*)d_in[7];
    float*       out           = (float*)d_out;

    constexpr int SMEM_WI  = (128 * DMSG + DMSG * HH) * 4;       // 168960
    constexpr int SMEM_ATT = (128 * DATT + DATT * HH) * 4;       // 154624
    constexpr int SMEM_MSG = (128 * (HH + 1) + HH * HH) * 4;     // 131584

    cudaFuncSetAttribute(k_gemm_wi,  cudaFuncAttributeMaxDynamicSharedMemorySize, SMEM_WI);
    cudaFuncSetAttribute(k_gemm_att, cudaFuncAttributeMaxDynamicSharedMemorySize, SMEM_ATT);
    cudaFuncSetAttribute(k_gemm_msg, cudaFuncAttributeMaxDynamicSharedMemorySize, SMEM_MSG);

    float *bias, *m0, *m1, *nei, *attnei;
    cudaGetSymbolAddress((void**)&bias,   g_bias2);
    cudaGetSymbolAddress((void**)&m0,     g_msg0);
    cudaGetSymbolAddress((void**)&m1,     g_msg1);
    cudaGetSymbolAddress((void**)&nei,    g_nei);
    cudaGetSymbolAddress((void**)&attnei, g_attnei);

    const int gb = (NBb + 127) / 128;   // 3907
    const int ga = NAa / 8;             // 31250

    // Loop-invariant precompute
    k_att_agg<<<ga, 256>>>(attfea, a2att, attnei);
    k_gemm_wi<<<gb, 256, SMEM_WI>>>(init_messages, W_i, bias, m0);
    k_gemm_att<<<gb, 256, SMEM_ATT>>>(attnei, attfea, W_h + HH * HH,
                                      b2a, b2revb, bias);

    // 5 message-passing iterations (DEPTH-1), ping-pong buffers
    float* cur = m0;
    float* nxt = m1;
    for (int it = 0; it < 5; ++it) {
        k_nei_agg<<<ga, 256>>>(cur, a2nei, nei);
        float* o = (it == 4) ? out : nxt;
        k_gemm_msg<<<gb, 256, SMEM_MSG>>>(nei, cur, W_h, b2a, b2revb, bias, o);
        float* t = cur; cur = nxt; nxt = t;
    }
}

// round 6
// speedup vs baseline: 1.1379x; 1.1379x over previous
#include <cuda_runtime.h>

// ---------------------------------------------------------------------------
// MPNEncoder: message-passing network, DEPTH=6, H=128.
//
//   inp        = init_messages @ W_i                      (once)
//   attnei[a]  = sum_j attfea[a2attached[a,j]]            (once)
//   bias2[b]   = inp[b] + (attnei[b2a[b]] - attfea[b2a[b2revb[b]]]) @ W_h[128:]
//   msg        = relu(inp)
//   5x: nei[a] = sum_j msg[a2nei[a,j]]
//       msg    = relu(bias2 + (nei[b2a] - msg[b2revb]) @ W_h[:128])
//
// GEMMs use fp32 SIMD (fma.rn.f32x2) with f32x2 lanes PAIRED OVER K:
// acc u64 = (sum over even k, sum over odd k) for one output column.
// A loads are contiguous ld.shared.b64 (no lane-duplication MOVs); B is
// repacked once per CTA into k-paired u64s. 512 threads/CTA, thread tile
// 4 rows x 8 columns (columns strided by 16 for conflict-free B loads).
// ---------------------------------------------------------------------------

constexpr int NBb  = 500000;
constexpr int NAa  = 250000;
constexpr int DMSG = 165;
constexpr int DATT = 151;
constexpr int HH   = 128;

__device__ float g_bias2 [(size_t)NBb * HH];
__device__ float g_msg0  [(size_t)NBb * HH];
__device__ float g_msg1  [(size_t)NBb * HH];
__device__ float g_nei   [(size_t)NAa * HH];
__device__ float g_attnei[(size_t)NAa * DATT];

typedef unsigned long long u64;

__device__ __forceinline__ u64 pack2(float lo, float hi) {
    u64 d;
    asm("mov.b64 %0, {%1, %2};" : "=l"(d) : "f"(lo), "f"(hi));
    return d;
}
__device__ __forceinline__ void unpack2(u64 v, float& lo, float& hi) {
    asm("mov.b64 {%0, %1}, %2;" : "=f"(lo), "=f"(hi) : "l"(v));
}
__device__ __forceinline__ void fma2(u64& d, u64 a, u64 b) {
    asm("fma.rn.f32x2 %0, %1, %2, %0;" : "+l"(d) : "l"(a), "l"(b));
}

// ---------------------------------------------------------------------------
// Core k-paired GEMM loop.
// sA: float[128][PITCHF] row-major (PITCHF even -> 8B aligned u64 pairs).
// sB: u64[KK][128], sB[kk][c] = (B[2kk][c], B[2kk+1][c]).
// Thread (tx in 0..15, ty in 0..31): rows ty*4..+3, cols {tx + 16j}, j=0..7.
// ---------------------------------------------------------------------------
template<int KK, int PITCHF>
__device__ __forceinline__ void gemm_kpair(const float* __restrict__ sA,
                                           const u64* __restrict__ sB,
                                           u64 (&acc)[4][8], int ty, int tx) {
    const float* pa = sA + ty * 4 * PITCHF;
    const u64*   pb = sB + tx;
    #pragma unroll 4
    for (int kk = 0; kk < KK; ++kk) {
        u64 a0 = *(const u64*)(pa + 0 * PITCHF + 2 * kk);
        u64 a1 = *(const u64*)(pa + 1 * PITCHF + 2 * kk);
        u64 a2 = *(const u64*)(pa + 2 * PITCHF + 2 * kk);
        u64 a3 = *(const u64*)(pa + 3 * PITCHF + 2 * kk);
        const u64* pk = pb + (size_t)kk * HH;
        #pragma unroll
        for (int j = 0; j < 8; ++j) {
            u64 b = pk[16 * j];
            fma2(acc[0][j], a0, b);
            fma2(acc[1][j], a1, b);
            fma2(acc[2][j], a2, b);
            fma2(acc[3][j], a3, b);
        }
    }
}

__device__ __forceinline__ void zero_acc(u64 (&acc)[4][8]) {
    #pragma unroll
    for (int i = 0; i < 4; ++i)
        #pragma unroll
        for (int j = 0; j < 8; ++j) acc[i][j] = 0ull;
}

// ---------------------------------------------------------------------------
// Kernel 1: inp = A @ W_i ; bias_out = inp ; msg_out = relu(inp).  K=165.
// ---------------------------------------------------------------------------
__global__ void __launch_bounds__(512, 1) k_gemm_wi(
    const float* __restrict__ A, const float* __restrict__ W,
    float* __restrict__ bias_out, float* __restrict__ msg_out)
{
    constexpr int KK = 83, PITCHF = 166;            // 165 padded to 166
    extern __shared__ float sm[];
    float* sA = sm;                                  // [128][166]
    u64*   sB = (u64*)(sm + 128 * PITCHF);           // [83][128]
    const int tid = threadIdx.x;

    for (int i = tid; i < KK * HH; i += 512) {
        int kk = i >> 7, c = i & 127;
        float lo = W[(2 * kk) * HH + c];
        float hi = (2 * kk + 1 < DMSG) ? W[(2 * kk + 1) * HH + c] : 0.f;
        sB[i] = pack2(lo, hi);
    }

    const long row0 = (long)blockIdx.x * 128;
    const int warp = tid >> 5, lane = tid & 31;
    for (int r = warp; r < 128; r += 16) {
        long b = row0 + r;
        bool valid = b < NBb;
        const float* src = A + (long)(valid ? b : 0) * DMSG;
        float* d = sA + r * PITCHF;
        for (int c = lane; c < PITCHF; c += 32)
            d[c] = (valid && c < DMSG) ? src[c] : 0.f;
    }
    __syncthreads();

    const int tx = tid & 15, ty = tid >> 4;
    u64 acc[4][8];
    zero_acc(acc);
    gemm_kpair<KK, PITCHF>(sA, sB, acc, ty, tx);

    #pragma unroll
    for (int i = 0; i < 4; ++i) {
        long r = row0 + ty * 4 + i;
        if (r < NBb) {
            #pragma unroll
            for (int j = 0; j < 8; ++j) {
                float lo, hi;
                unpack2(acc[i][j], lo, hi);
                float v = lo + hi;
                int c = tx + 16 * j;
                bias_out[r * HH + c] = v;
                msg_out[r * HH + c]  = fmaxf(v, 0.f);
            }
        }
    }
}

// ---------------------------------------------------------------------------
// Kernel 2: attnei[a] = sum_j attfea[a2attached[a,j]]   (warp per atom)
// ---------------------------------------------------------------------------
__global__ void __launch_bounds__(256) k_att_agg(
    const float* __restrict__ attfea, const int* __restrict__ a2att,
    float* __restrict__ attnei)
{
    const int warp = threadIdx.x >> 5, lane = threadIdx.x & 31;
    const int a = blockIdx.x * 8 + warp;
    if (a >= NAa) return;

    int idx[6];
    #pragma unroll
    for (int j = 0; j < 6; ++j) idx[j] = a2att[a * 6 + j];

    float acc[5] = {0.f, 0.f, 0.f, 0.f, 0.f};
    #pragma unroll
    for (int j = 0; j < 6; ++j) {
        const float* p = attfea + (long)idx[j] * DATT;
        #pragma unroll
        for (int t = 0; t < 5; ++t) {
            int c = t * 32 + lane;
            if (c < DATT) acc[t] += p[c];
        }
    }
    float* o = attnei + (long)a * DATT;
    #pragma unroll
    for (int t = 0; t < 5; ++t) {
        int c = t * 32 + lane;
        if (c < DATT) o[c] = acc[t];
    }
}

// ---------------------------------------------------------------------------
// Kernel 3: bias2 += (attnei[b2a[b]] - attfea[b2a[b2revb[b]]]) @ W_h[128:279]
// K = 151 -> 76 pairs.
// ---------------------------------------------------------------------------
__global__ void __launch_bounds__(512, 1) k_gemm_att(
    const float* __restrict__ attnei, const float* __restrict__ attfea,
    const float* __restrict__ Wh_att, const int* __restrict__ b2a,
    const int* __restrict__ b2revb, float* __restrict__ bias)
{
    constexpr int KK = 76, PITCHF = 152;
    extern __shared__ float sm[];
    float* sA = sm;                                  // [128][152]
    u64*   sB = (u64*)(sm + 128 * PITCHF);           // [76][128]
    const int tid = threadIdx.x;

    for (int i = tid; i < KK * HH; i += 512) {
        int kk = i >> 7, c = i & 127;
        float lo = Wh_att[(2 * kk) * HH + c];
        float hi = (2 * kk + 1 < DATT) ? Wh_att[(2 * kk + 1) * HH + c] : 0.f;
        sB[i] = pack2(lo, hi);
    }

    const long row0 = (long)blockIdx.x * 128;
    const int warp = tid >> 5, lane = tid & 31;
    for (int r = warp; r < 128; r += 16) {
        long b = row0 + r;
        bool valid = b < NBb;
        int ia = 0, ir = 0;
        if (valid) { ia = b2a[b]; ir = b2a[b2revb[b]]; }
        const float* pa = attnei + (long)ia * DATT;
        const float* pr = attfea + (long)ir * DATT;
        float* d = sA + r * PITCHF;
        for (int c = lane; c < PITCHF; c += 32)
            d[c] = (valid && c < DATT) ? (pa[c] - pr[c]) : 0.f;
    }
    __syncthreads();

    const int tx = tid & 15, ty = tid >> 4;
    u64 acc[4][8];
    zero_acc(acc);
    gemm_kpair<KK, PITCHF>(sA, sB, acc, ty, tx);

    #pragma unroll
    for (int i = 0; i < 4; ++i) {
        long r = row0 + ty * 4 + i;
        if (r < NBb) {
            #pragma unroll
            for (int j = 0; j < 8; ++j) {
                float lo, hi;
                unpack2(acc[i][j], lo, hi);
                int c = tx + 16 * j;
                bias[r * HH + c] += lo + hi;
            }
        }
    }
}

// ---------------------------------------------------------------------------
// Kernel 4: nei[a] = sum_j msg[a2nei[a,j]]   (warp per atom, float4 lanes)
// ---------------------------------------------------------------------------
__global__ void __launch_bounds__(256) k_nei_agg(
    const float* __restrict__ msg, const int* __restrict__ a2nei,
    float* __restrict__ nei)
{
    const int warp = threadIdx.x >> 5, lane = threadIdx.x & 31;
    const int a = blockIdx.x * 8 + warp;
    if (a >= NAa) return;

    int idx[6];
    #pragma unroll
    for (int j = 0; j < 6; ++j) idx[j] = a2nei[a * 6 + j];

    float4 acc = make_float4(0.f, 0.f, 0.f, 0.f);
    #pragma unroll
    for (int j = 0; j < 6; ++j) {
        float4 v = *(const float4*)(msg + (long)idx[j] * HH + lane * 4);
        acc.x += v.x; acc.y += v.y; acc.z += v.z; acc.w += v.w;
    }
    *(float4*)(nei + (long)a * HH + lane * 4) = acc;
}

// ---------------------------------------------------------------------------
// Kernel 5: msg_out = relu(bias2 + (nei[b2a] - msg_in[b2revb]) @ W_h[:128])
// K = 128 -> 64 pairs.
// ---------------------------------------------------------------------------
__global__ void __launch_bounds__(512, 1) k_gemm_msg(
    const float* __restrict__ nei, const float* __restrict__ msg_in,
    const float* __restrict__ Wh, const int* __restrict__ b2a,
    const int* __restrict__ b2revb, const float* __restrict__ bias,
    float* __restrict__ msg_out)
{
    constexpr int KK = 64, PITCHF = 130;
    extern __shared__ float sm[];
    float* sA = sm;                                  // [128][130]
    u64*   sB = (u64*)(sm + 128 * PITCHF);           // [64][128]
    const int tid = threadIdx.x;

    for (int i = tid; i < KK * HH; i += 512) {
        int kk = i >> 7, c = i & 127;
        sB[i] = pack2(Wh[(2 * kk) * HH + c], Wh[(2 * kk + 1) * HH + c]);
    }

    const long row0 = (long)blockIdx.x * 128;
    const int warp = tid >> 5, lane = tid & 31;
    for (int r = warp; r < 128; r += 16) {
        long b = row0 + r;
        bool valid = b < NBb;
        int ia = valid ? b2a[b] : 0;
        int ib = valid ? b2revb[b] : 0;
        float4 x = *(const float4*)(nei + (long)ia * HH + lane * 4);
        float4 y = *(const float4*)(msg_in + (long)ib * HH + lane * 4);
        float* d = sA + r * PITCHF + lane * 4;
        d[0] = valid ? (x.x - y.x) : 0.f;
        d[1] = valid ? (x.y - y.y) : 0.f;
        d[2] = valid ? (x.z - y.z) : 0.f;
        d[3] = valid ? (x.w - y.w) : 0.f;
    }
    __syncthreads();

    const int tx = tid & 15, ty = tid >> 4;
    u64 acc[4][8];
    zero_acc(acc);
    gemm_kpair<KK, PITCHF>(sA, sB, acc, ty, tx);

    #pragma unroll
    for (int i = 0; i < 4; ++i) {
        long r = row0 + ty * 4 + i;
        if (r < NBb) {
            #pragma unroll
            for (int j = 0; j < 8; ++j) {
                float lo, hi;
                unpack2(acc[i][j], lo, hi);
                int c = tx + 16 * j;
                msg_out[r * HH + c] = fmaxf(bias[r * HH + c] + lo + hi, 0.f);
            }
        }
    }
}

// ---------------------------------------------------------------------------
// Launch
// ---------------------------------------------------------------------------
extern "C" void kernel_launch(void* const* d_in, const int* in_sizes, int n_in,
                              void* d_out, int out_size) {
    (void)in_sizes; (void)n_in; (void)out_size;

    const float* init_messages = (const float*)d_in[0];
    const float* attfea        = (const float*)d_in[1];
    const float* W_i           = (const float*)d_in[2];
    const float* W_h           = (const float*)d_in[3];  // [279][128]
    const int*   a2nei         = (const int*)d_in[4];
    const int*   a2att         = (const int*)d_in[5];
    const int*   b2a           = (const int*)d_in[6];
    const int*   b2revb        = (const int*)d_in[7];
    float*       out           = (float*)d_out;

    constexpr int SMEM_WI  = 128 * 166 * 4 + 83 * 128 * 8;   // 169,984
    constexpr int SMEM_ATT = 128 * 152 * 4 + 76 * 128 * 8;   // 155,648
    constexpr int SMEM_MSG = 128 * 130 * 4 + 64 * 128 * 8;   // 132,096

    cudaFuncSetAttribute(k_gemm_wi,  cudaFuncAttributeMaxDynamicSharedMemorySize, SMEM_WI);
    cudaFuncSetAttribute(k_gemm_att, cudaFuncAttributeMaxDynamicSharedMemorySize, SMEM_ATT);
    cudaFuncSetAttribute(k_gemm_msg, cudaFuncAttributeMaxDynamicSharedMemorySize, SMEM_MSG);

    float *bias, *m0, *m1, *nei, *attnei;
    cudaGetSymbolAddress((void**)&bias,   g_bias2);
    cudaGetSymbolAddress((void**)&m0,     g_msg0);
    cudaGetSymbolAddress((void**)&m1,     g_msg1);
    cudaGetSymbolAddress((void**)&nei,    g_nei);
    cudaGetSymbolAddress((void**)&attnei, g_attnei);

    const int gb = (NBb + 127) / 128;   // 3907
    const int ga = NAa / 8;             // 31250

    // Loop-invariant precompute
    k_att_agg<<<ga, 256>>>(attfea, a2att, attnei);
    k_gemm_wi<<<gb, 512, SMEM_WI>>>(init_messages, W_i, bias, m0);
    k_gemm_att<<<gb, 512, SMEM_ATT>>>(attnei, attfea, W_h + HH * HH,
                                      b2a, b2revb, bias);

    // 5 message-passing iterations (DEPTH-1), ping-pong buffers
    float* cur = m0;
    float* nxt = m1;
    for (int it = 0; it < 5; ++it) {
        k_nei_agg<<<ga, 256>>>(cur, a2nei, nei);
        float* o = (it == 4) ? out : nxt;
        k_gemm_msg<<<gb, 512, SMEM_MSG>>>(nei, cur, W_h, b2a, b2revb, bias, o);
        float* t = cur; cur = nxt; nxt = t;
    }
}